// round 3
// baseline (speedup 1.0000x reference)
#include <cuda_runtime.h>
#include <cuda_bf16.h>
#include <cstdint>

#define N_NODES 40000
#define E_EDGES 640000
#define D 128

// ---------------- scratch (allocation-free: __device__ globals) ----------------
__device__ float g_u[N_NODES * D];   // A @ Wl  (to be aggregated)
__device__ float g_v[N_NODES * D];   // A @ Wr  (root term)
__device__ float g_h[N_NODES * D];   // layer output
__device__ int   g_deg[N_NODES];
__device__ int   g_rowptr[N_NODES + 1];
__device__ int   g_fill[N_NODES];
__device__ int   g_col[E_EDGES];
__device__ int   g_is32;             // 1 if edge_index is int32, 0 if int64

// ---------------- dtype probe ----------------
__global__ void detect_kernel(const void* __restrict__ edge) {
    const long long* e64 = (const long long*)edge;
    int bad = 0;
    #pragma unroll
    for (int i = 0; i < 8; i++) {
        long long v = e64[i];
        if (v < 0 || v >= N_NODES) bad = 1;
    }
    g_is32 = bad;  // out-of-range as int64 => actually int32 data
}

__device__ __forceinline__ int edge_at(const void* edge, long long idx) {
    if (g_is32) return ((const int*)edge)[idx];
    return (int)((const long long*)edge)[idx];
}

// ---------------- CSR build ----------------
__global__ void zero_deg_kernel() {
    int i = blockIdx.x * blockDim.x + threadIdx.x;
    if (i < N_NODES) g_deg[i] = 0;
}

__global__ void count_deg_kernel(const void* __restrict__ edge) {
    int i = blockIdx.x * blockDim.x + threadIdx.x;
    if (i < E_EDGES) {
        int dst = edge_at(edge, (long long)E_EDGES + i);
        atomicAdd(&g_deg[dst], 1);
    }
}

// single-block exclusive scan of g_deg -> g_rowptr (and init g_fill)
__global__ void scan_kernel() {
    __shared__ int partial[1024];
    const int CH = (N_NODES + 1023) / 1024;  // 40
    int t = threadIdx.x;
    int base = t * CH;
    int s = 0;
    for (int j = 0; j < CH; j++) {
        int idx = base + j;
        if (idx < N_NODES) s += g_deg[idx];
    }
    partial[t] = s;
    __syncthreads();
    // Hillis-Steele inclusive scan
    for (int off = 1; off < 1024; off <<= 1) {
        int v = 0;
        if (t >= off) v = partial[t - off];
        __syncthreads();
        partial[t] += v;
        __syncthreads();
    }
    int run = partial[t] - s;  // exclusive prefix for this chunk
    for (int j = 0; j < CH; j++) {
        int idx = base + j;
        if (idx < N_NODES) {
            g_rowptr[idx] = run;
            g_fill[idx]   = run;
            run += g_deg[idx];
        }
    }
    if (t == 1023) g_rowptr[N_NODES] = partial[1023];
}

__global__ void fill_col_kernel(const void* __restrict__ edge) {
    int i = blockIdx.x * blockDim.x + threadIdx.x;
    if (i < E_EDGES) {
        int src = edge_at(edge, i);
        int dst = edge_at(edge, (long long)E_EDGES + i);
        int pos = atomicAdd(&g_fill[dst], 1);
        g_col[pos] = src;
    }
}

// ---------------- fused dual GEMM: g_u = A@Wl, g_v = A@Wr ----------------
// A: [nrows, 128] row-major (either external x, or g_h when use_h != 0)
// W: [128, 128] row-major. Tiling: BM=64, BN=128 (full), BK=16; 256 threads.
#define BM 64
#define BK 16

__global__ void __launch_bounds__(256, 2)
gemm_dual_kernel(const float* __restrict__ Aext, int use_h,
                 const float* __restrict__ Wl,
                 const float* __restrict__ Wr) {
    __shared__ float sA[BK][BM];
    __shared__ float sWl[BK][D];
    __shared__ float sWr[BK][D];

    const float* A = use_h ? g_h : Aext;

    const int block_row = blockIdx.x * BM;
    const int tid = threadIdx.x;
    const int tr = tid >> 5;       // 0..7  -> rows tr*8 .. tr*8+7
    const int tc = tid & 31;       // 0..31 -> cols tc*4 .. tc*4+3

    float accU[8][4] = {};
    float accV[8][4] = {};

    for (int k0 = 0; k0 < D; k0 += BK) {
        // A tile (BM x BK), stored transposed for broadcast reads
        #pragma unroll
        for (int i = tid; i < BM * BK; i += 256) {
            int m = i / BK, k = i % BK;
            sA[k][m] = A[(size_t)(block_row + m) * D + k0 + k];
        }
        // W tiles (BK x 128)
        #pragma unroll
        for (int i = tid; i < BK * D; i += 256) {
            int k = i / D, n = i % D;
            sWl[k][n] = Wl[(size_t)(k0 + k) * D + n];
            sWr[k][n] = Wr[(size_t)(k0 + k) * D + n];
        }
        __syncthreads();

        #pragma unroll
        for (int k = 0; k < BK; k++) {
            float a[8];
            #pragma unroll
            for (int i = 0; i < 8; i++) a[i] = sA[k][tr * 8 + i];
            float4 wl4 = *(const float4*)&sWl[k][tc * 4];
            float4 wr4 = *(const float4*)&sWr[k][tc * 4];
            float wl[4] = {wl4.x, wl4.y, wl4.z, wl4.w};
            float wr[4] = {wr4.x, wr4.y, wr4.z, wr4.w};
            #pragma unroll
            for (int i = 0; i < 8; i++) {
                #pragma unroll
                for (int j = 0; j < 4; j++) {
                    accU[i][j] = fmaf(a[i], wl[j], accU[i][j]);
                    accV[i][j] = fmaf(a[i], wr[j], accV[i][j]);
                }
            }
        }
        __syncthreads();
    }

    #pragma unroll
    for (int i = 0; i < 8; i++) {
        size_t row = block_row + tr * 8 + i;
        float4 u4 = make_float4(accU[i][0], accU[i][1], accU[i][2], accU[i][3]);
        float4 v4 = make_float4(accV[i][0], accV[i][1], accV[i][2], accV[i][3]);
        *(float4*)&g_u[row * D + tc * 4] = u4;
        *(float4*)&g_v[row * D + tc * 4] = v4;
    }
}

// ---------------- aggregate: g_h = relu(mean_j g_u[col[j]] + b + g_v) ----------------
// one warp per destination node; each lane owns 4 contiguous floats (float4)
__global__ void aggregate_kernel(const float* __restrict__ b) {
    int warp = (blockIdx.x * blockDim.x + threadIdx.x) >> 5;
    int lane = threadIdx.x & 31;
    if (warp >= N_NODES) return;

    int start = g_rowptr[warp];
    int end   = g_rowptr[warp + 1];

    float ax = 0.f, ay = 0.f, az = 0.f, aw = 0.f;
    for (int j = start; j < end; j++) {
        int s = g_col[j];
        float4 t = *(const float4*)&g_u[(size_t)s * D + lane * 4];
        ax += t.x; ay += t.y; az += t.z; aw += t.w;
    }
    float inv = 1.0f / fmaxf((float)(end - start), 1.0f);
    float4 vv = *(const float4*)&g_v[(size_t)warp * D + lane * 4];
    float4 bb = *(const float4*)&b[lane * 4];
    float4 o;
    o.x = fmaxf(fmaf(ax, inv, bb.x + vv.x), 0.f);
    o.y = fmaxf(fmaf(ay, inv, bb.y + vv.y), 0.f);
    o.z = fmaxf(fmaf(az, inv, bb.z + vv.z), 0.f);
    o.w = fmaxf(fmaf(aw, inv, bb.w + vv.w), 0.f);
    *(float4*)&g_h[(size_t)warp * D + lane * 4] = o;
}

// ---------------- final: out[i] = g_h[i,:] . Wo[:,0] + bo ----------------
__global__ void final_kernel(const float* __restrict__ Wo,
                             const float* __restrict__ bo,
                             float* __restrict__ out) {
    int warp = (blockIdx.x * blockDim.x + threadIdx.x) >> 5;
    int lane = threadIdx.x & 31;
    if (warp >= N_NODES) return;

    float4 hh = *(const float4*)&g_h[(size_t)warp * D + lane * 4];
    float4 ww = *(const float4*)&Wo[lane * 4];
    float s = hh.x * ww.x + hh.y * ww.y + hh.z * ww.z + hh.w * ww.w;
    #pragma unroll
    for (int off = 16; off > 0; off >>= 1)
        s += __shfl_xor_sync(0xFFFFFFFF, s, off);
    if (lane == 0) out[warp] = s + bo[0];
}

// ---------------- launch ----------------
extern "C" void kernel_launch(void* const* d_in, const int* in_sizes, int n_in,
                              void* d_out, int out_size) {
    const float* x    = (const float*)d_in[0];
    const void*  edge = d_in[1];
    const float* W1l  = (const float*)d_in[2];
    const float* b1   = (const float*)d_in[3];
    const float* W1r  = (const float*)d_in[4];
    const float* W2l  = (const float*)d_in[5];
    const float* b2   = (const float*)d_in[6];
    const float* W2r  = (const float*)d_in[7];
    const float* Wo   = (const float*)d_in[8];
    const float* bo   = (const float*)d_in[9];
    float*       out  = (float*)d_out;

    // CSR build
    detect_kernel<<<1, 1>>>(edge);
    zero_deg_kernel<<<(N_NODES + 255) / 256, 256>>>();
    count_deg_kernel<<<(E_EDGES + 255) / 256, 256>>>(edge);
    scan_kernel<<<1, 1024>>>();
    fill_col_kernel<<<(E_EDGES + 255) / 256, 256>>>(edge);

    const int gemm_grid = N_NODES / BM;                 // 625
    const int agg_grid  = (N_NODES * 32 + 255) / 256;   // 5000

    // layer 1
    gemm_dual_kernel<<<gemm_grid, 256>>>(x, 0, W1l, W1r);
    aggregate_kernel<<<agg_grid, 256>>>(b1);
    // layer 2
    gemm_dual_kernel<<<gemm_grid, 256>>>(nullptr, 1, W2l, W2r);
    aggregate_kernel<<<agg_grid, 256>>>(b2);
    // output
    final_kernel<<<agg_grid, 256>>>(Wo, bo, out);
}

// round 4
// speedup vs baseline: 1.5433x; 1.5433x over previous
#include <cuda_runtime.h>
#include <cuda_bf16.h>
#include <cstdint>

#define N_NODES 40000
#define E_EDGES 640000
#define D 128

#define SCAN_CHUNK 1024
#define SCAN_BLOCKS ((N_NODES + SCAN_CHUNK - 1) / SCAN_CHUNK)  // 40

// ---------------- scratch (allocation-free: __device__ globals) ----------------
__device__ float g_u[N_NODES * D];   // A @ Wl  (to be aggregated)
__device__ float g_v[N_NODES * D];   // A @ Wr  (root term)
__device__ float g_h[N_NODES * D];   // layer output
__device__ int   g_deg[N_NODES];
__device__ int   g_rowptr[N_NODES + 1];
__device__ int   g_fill[N_NODES];
__device__ int   g_col[E_EDGES];
__device__ int   g_blksum[SCAN_BLOCKS];
__device__ int   g_is32;             // 1 if edge_index is int32, 0 if int64

// ---------------- zero degrees + dtype probe (fused) ----------------
__global__ void zero_detect_kernel(const void* __restrict__ edge) {
    int i = blockIdx.x * blockDim.x + threadIdx.x;
    if (i < N_NODES) g_deg[i] = 0;
    if (i == 0) {
        const long long* e64 = (const long long*)edge;
        int bad = 0;
        #pragma unroll
        for (int j = 0; j < 8; j++) {
            long long v = e64[j];
            if (v < 0 || v >= N_NODES) bad = 1;
        }
        g_is32 = bad;  // out-of-range as int64 => actually int32 data
    }
}

__device__ __forceinline__ int edge_at(const void* edge, long long idx) {
    if (g_is32) return ((const int*)edge)[idx];
    return (int)((const long long*)edge)[idx];
}

// ---------------- CSR build ----------------
__global__ void count_deg_kernel(const void* __restrict__ edge) {
    int i = blockIdx.x * blockDim.x + threadIdx.x;
    if (i < E_EDGES) {
        int dst = edge_at(edge, (long long)E_EDGES + i);
        atomicAdd(&g_deg[dst], 1);
    }
}

// ---- scan phase 1: per-chunk (1024) sums, 40 blocks x 256 threads ----
__global__ void scan1_kernel() {
    int base = blockIdx.x * SCAN_CHUNK + threadIdx.x * 4;
    int s = 0;
    #pragma unroll
    for (int j = 0; j < 4; j++) {
        int idx = base + j;
        if (idx < N_NODES) s += g_deg[idx];
    }
    #pragma unroll
    for (int off = 16; off > 0; off >>= 1)
        s += __shfl_xor_sync(0xFFFFFFFF, s, off);
    __shared__ int ws[8];
    int lane = threadIdx.x & 31, wid = threadIdx.x >> 5;
    if (lane == 0) ws[wid] = s;
    __syncthreads();
    if (threadIdx.x == 0) {
        int t = 0;
        #pragma unroll
        for (int j = 0; j < 8; j++) t += ws[j];
        g_blksum[blockIdx.x] = t;
    }
}

// ---- scan phase 2: exclusive scan of 40 chunk sums (1 tiny block) ----
__global__ void scan2_kernel() {
    __shared__ int sb[SCAN_BLOCKS];
    if (threadIdx.x < SCAN_BLOCKS) sb[threadIdx.x] = g_blksum[threadIdx.x];
    __syncthreads();
    if (threadIdx.x == 0) {
        int run = 0;
        for (int j = 0; j < SCAN_BLOCKS; j++) {
            int t = sb[j];
            sb[j] = run;
            run += t;
        }
        g_rowptr[N_NODES] = run;  // == E_EDGES
    }
    __syncthreads();
    if (threadIdx.x < SCAN_BLOCKS) g_blksum[threadIdx.x] = sb[threadIdx.x];
}

// ---- scan phase 3: local scan within chunk + chunk offset -> rowptr/fill ----
__global__ void scan3_kernel() {
    __shared__ int tsum[256];
    int tid = threadIdx.x;
    int base = blockIdx.x * SCAN_CHUNK + tid * 4;
    int d0 = 0, d1 = 0, d2 = 0, d3 = 0;
    if (base + 0 < N_NODES) d0 = g_deg[base + 0];
    if (base + 1 < N_NODES) d1 = g_deg[base + 1];
    if (base + 2 < N_NODES) d2 = g_deg[base + 2];
    if (base + 3 < N_NODES) d3 = g_deg[base + 3];
    int t4 = d0 + d1 + d2 + d3;

    // inclusive scan of t4 across 256 threads (warp shfl + shared)
    int lane = tid & 31, wid = tid >> 5;
    int v = t4;
    #pragma unroll
    for (int off = 1; off < 32; off <<= 1) {
        int n = __shfl_up_sync(0xFFFFFFFF, v, off);
        if (lane >= off) v += n;
    }
    __shared__ int wsum[8];
    if (lane == 31) wsum[wid] = v;
    __syncthreads();
    int woff = 0;
    #pragma unroll
    for (int j = 0; j < 8; j++) woff += (j < wid) ? wsum[j] : 0;
    int excl = v - t4 + woff + g_blksum[blockIdx.x];

    int r0 = excl;
    int r1 = r0 + d0;
    int r2 = r1 + d1;
    int r3 = r2 + d2;
    if (base + 0 < N_NODES) { g_rowptr[base + 0] = r0; g_fill[base + 0] = r0; }
    if (base + 1 < N_NODES) { g_rowptr[base + 1] = r1; g_fill[base + 1] = r1; }
    if (base + 2 < N_NODES) { g_rowptr[base + 2] = r2; g_fill[base + 2] = r2; }
    if (base + 3 < N_NODES) { g_rowptr[base + 3] = r3; g_fill[base + 3] = r3; }
    (void)tsum;
}

__global__ void fill_col_kernel(const void* __restrict__ edge) {
    int i = blockIdx.x * blockDim.x + threadIdx.x;
    if (i < E_EDGES) {
        int src = edge_at(edge, i);
        int dst = edge_at(edge, (long long)E_EDGES + i);
        int pos = atomicAdd(&g_fill[dst], 1);
        g_col[pos] = src;
    }
}

// ---------------- fused dual GEMM: g_u = A@Wl, g_v = A@Wr ----------------
// A: [nrows, 128] row-major (either external x, or g_h when use_h != 0)
// W: [128, 128] row-major. Tiling: BM=64, BN=128 (full), BK=16; 256 threads.
#define BM 64
#define BK 16

__global__ void __launch_bounds__(256, 2)
gemm_dual_kernel(const float* __restrict__ Aext, int use_h,
                 const float* __restrict__ Wl,
                 const float* __restrict__ Wr) {
    __shared__ float sA[BK][BM];
    __shared__ float sWl[BK][D];
    __shared__ float sWr[BK][D];

    const float* A = use_h ? g_h : Aext;

    const int block_row = blockIdx.x * BM;
    const int tid = threadIdx.x;
    const int tr = tid >> 5;       // 0..7  -> rows tr*8 .. tr*8+7
    const int tc = tid & 31;       // 0..31 -> cols tc*4 .. tc*4+3

    // A-tile fill indices: one float4 per thread per k0 step
    const int am = tid >> 2;       // 0..63  (row within tile)
    const int aq = tid & 3;        // 0..3   (k-quad)

    float accU[8][4] = {};
    float accV[8][4] = {};

    for (int k0 = 0; k0 < D; k0 += BK) {
        // A tile (BM x BK) via float4, stored transposed
        {
            float4 av = *(const float4*)&A[(size_t)(block_row + am) * D + k0 + aq * 4];
            sA[aq * 4 + 0][am] = av.x;
            sA[aq * 4 + 1][am] = av.y;
            sA[aq * 4 + 2][am] = av.z;
            sA[aq * 4 + 3][am] = av.w;
        }
        // W tiles (BK x 128) via float4: 2 per thread per W
        #pragma unroll
        for (int w = 0; w < 2; w++) {
            int j = tid + w * 256;
            int k = j >> 5;
            int n4 = (j & 31) * 4;
            *(float4*)&sWl[k][n4] = *(const float4*)&Wl[(size_t)(k0 + k) * D + n4];
            *(float4*)&sWr[k][n4] = *(const float4*)&Wr[(size_t)(k0 + k) * D + n4];
        }
        __syncthreads();

        #pragma unroll
        for (int k = 0; k < BK; k++) {
            float4 a0 = *(const float4*)&sA[k][tr * 8];
            float4 a1 = *(const float4*)&sA[k][tr * 8 + 4];
            float a[8] = {a0.x, a0.y, a0.z, a0.w, a1.x, a1.y, a1.z, a1.w};
            float4 wl4 = *(const float4*)&sWl[k][tc * 4];
            float4 wr4 = *(const float4*)&sWr[k][tc * 4];
            float wl[4] = {wl4.x, wl4.y, wl4.z, wl4.w};
            float wr[4] = {wr4.x, wr4.y, wr4.z, wr4.w};
            #pragma unroll
            for (int i = 0; i < 8; i++) {
                #pragma unroll
                for (int j = 0; j < 4; j++) {
                    accU[i][j] = fmaf(a[i], wl[j], accU[i][j]);
                    accV[i][j] = fmaf(a[i], wr[j], accV[i][j]);
                }
            }
        }
        __syncthreads();
    }

    #pragma unroll
    for (int i = 0; i < 8; i++) {
        size_t row = block_row + tr * 8 + i;
        float4 u4 = make_float4(accU[i][0], accU[i][1], accU[i][2], accU[i][3]);
        float4 v4 = make_float4(accV[i][0], accV[i][1], accV[i][2], accV[i][3]);
        *(float4*)&g_u[row * D + tc * 4] = u4;
        *(float4*)&g_v[row * D + tc * 4] = v4;
    }
}

// ---------------- aggregate: g_h = relu(mean_j g_u[col[j]] + b + g_v) ----------------
// one warp per destination node; each lane owns 4 contiguous floats (float4)
__global__ void aggregate_kernel(const float* __restrict__ b) {
    int warp = (blockIdx.x * blockDim.x + threadIdx.x) >> 5;
    int lane = threadIdx.x & 31;
    if (warp >= N_NODES) return;

    int start = g_rowptr[warp];
    int end   = g_rowptr[warp + 1];

    float ax = 0.f, ay = 0.f, az = 0.f, aw = 0.f;
    for (int j = start; j < end; j++) {
        int s = g_col[j];
        float4 t = *(const float4*)&g_u[(size_t)s * D + lane * 4];
        ax += t.x; ay += t.y; az += t.z; aw += t.w;
    }
    float inv = 1.0f / fmaxf((float)(end - start), 1.0f);
    float4 vv = *(const float4*)&g_v[(size_t)warp * D + lane * 4];
    float4 bb = *(const float4*)&b[lane * 4];
    float4 o;
    o.x = fmaxf(fmaf(ax, inv, bb.x + vv.x), 0.f);
    o.y = fmaxf(fmaf(ay, inv, bb.y + vv.y), 0.f);
    o.z = fmaxf(fmaf(az, inv, bb.z + vv.z), 0.f);
    o.w = fmaxf(fmaf(aw, inv, bb.w + vv.w), 0.f);
    *(float4*)&g_h[(size_t)warp * D + lane * 4] = o;
}

// ---------------- fused aggregate + final gemv (layer 2) ----------------
// out[i] = relu(mean + b + v)[i,:] . Wo[:,0] + bo
__global__ void aggregate_final_kernel(const float* __restrict__ b,
                                       const float* __restrict__ Wo,
                                       const float* __restrict__ bo,
                                       float* __restrict__ out) {
    int warp = (blockIdx.x * blockDim.x + threadIdx.x) >> 5;
    int lane = threadIdx.x & 31;
    if (warp >= N_NODES) return;

    int start = g_rowptr[warp];
    int end   = g_rowptr[warp + 1];

    float ax = 0.f, ay = 0.f, az = 0.f, aw = 0.f;
    for (int j = start; j < end; j++) {
        int s = g_col[j];
        float4 t = *(const float4*)&g_u[(size_t)s * D + lane * 4];
        ax += t.x; ay += t.y; az += t.z; aw += t.w;
    }
    float inv = 1.0f / fmaxf((float)(end - start), 1.0f);
    float4 vv = *(const float4*)&g_v[(size_t)warp * D + lane * 4];
    float4 bb = *(const float4*)&b[lane * 4];
    float ox = fmaxf(fmaf(ax, inv, bb.x + vv.x), 0.f);
    float oy = fmaxf(fmaf(ay, inv, bb.y + vv.y), 0.f);
    float oz = fmaxf(fmaf(az, inv, bb.z + vv.z), 0.f);
    float ow = fmaxf(fmaf(aw, inv, bb.w + vv.w), 0.f);

    float4 ww = *(const float4*)&Wo[lane * 4];
    float s = ox * ww.x + oy * ww.y + oz * ww.z + ow * ww.w;
    #pragma unroll
    for (int off = 16; off > 0; off >>= 1)
        s += __shfl_xor_sync(0xFFFFFFFF, s, off);
    if (lane == 0) out[warp] = s + bo[0];
}

// ---------------- launch ----------------
extern "C" void kernel_launch(void* const* d_in, const int* in_sizes, int n_in,
                              void* d_out, int out_size) {
    const float* x    = (const float*)d_in[0];
    const void*  edge = d_in[1];
    const float* W1l  = (const float*)d_in[2];
    const float* b1   = (const float*)d_in[3];
    const float* W1r  = (const float*)d_in[4];
    const float* W2l  = (const float*)d_in[5];
    const float* b2   = (const float*)d_in[6];
    const float* W2r  = (const float*)d_in[7];
    const float* Wo   = (const float*)d_in[8];
    const float* bo   = (const float*)d_in[9];
    float*       out  = (float*)d_out;

    // CSR build
    zero_detect_kernel<<<(N_NODES + 255) / 256, 256>>>(edge);
    count_deg_kernel<<<(E_EDGES + 255) / 256, 256>>>(edge);
    scan1_kernel<<<SCAN_BLOCKS, 256>>>();
    scan2_kernel<<<1, 64>>>();
    scan3_kernel<<<SCAN_BLOCKS, 256>>>();
    fill_col_kernel<<<(E_EDGES + 255) / 256, 256>>>(edge);

    const int gemm_grid = N_NODES / BM;                 // 625
    const int agg_grid  = (N_NODES * 32 + 255) / 256;   // 5000

    // layer 1
    gemm_dual_kernel<<<gemm_grid, 256>>>(x, 0, W1l, W1r);
    aggregate_kernel<<<agg_grid, 256>>>(b1);
    // layer 2
    gemm_dual_kernel<<<gemm_grid, 256>>>(nullptr, 1, W2l, W2r);
    aggregate_final_kernel<<<agg_grid, 256>>>(b2, Wo, bo, out);
}